// round 3
// baseline (speedup 1.0000x reference)
#include <cuda_runtime.h>
#include <cuda_bf16.h>
#include <cstdint>

#define N_NODES 100000
#define C_DIM   256
#define CSR_CAP 3400000
#define SCAN_B  1024

// ---------------- device scratch (no allocations allowed) ----------------
__device__ int   g_deg[N_NODES];
__device__ int   g_offs[N_NODES + 1];
__device__ int   g_cursor[N_NODES];
__device__ float g_dis[N_NODES];
__device__ int   g_blockSums[SCAN_B];
__device__ int   g_csr_src[CSR_CAP];
__device__ float g_csr_w[CSR_CAP];
__device__ float g_bufT[(size_t)N_NODES * C_DIM];   // transformed features (X@W)
__device__ float g_bufH[(size_t)N_NODES * C_DIM];   // aggregated+activated features

// ---------------- degree / normalization ----------------
__global__ void k_deg_init() {
    int i = blockIdx.x * blockDim.x + threadIdx.x;
    if (i < N_NODES) g_deg[i] = 1;   // self-loop
}

__global__ void k_hist(const int* __restrict__ ei, int E) {
    for (int e = blockIdx.x * blockDim.x + threadIdx.x; e < E;
         e += gridDim.x * blockDim.x) {
        atomicAdd(&g_deg[ei[E + e]], 1);   // dst row
    }
}

__global__ void k_dis() {
    int i = blockIdx.x * blockDim.x + threadIdx.x;
    if (i < N_NODES) g_dis[i] = rsqrtf((float)g_deg[i]);
}

// ---------------- exclusive scan of degrees -> CSR row offsets ----------------
__global__ void k_scan1() {
    __shared__ int s[SCAN_B];
    int tid = threadIdx.x;
    int i = blockIdx.x * SCAN_B + tid;
    int v = (i < N_NODES) ? g_deg[i] : 0;
    s[tid] = v;
    __syncthreads();
#pragma unroll
    for (int off = 1; off < SCAN_B; off <<= 1) {
        int a = (tid >= off) ? s[tid - off] : 0;
        __syncthreads();
        s[tid] += a;
        __syncthreads();
    }
    if (i < N_NODES) g_offs[i] = s[tid] - v;          // block-local exclusive
    if (tid == SCAN_B - 1) g_blockSums[blockIdx.x] = s[tid];
}

__global__ void k_scan2(int nblk) {
    __shared__ int s[SCAN_B];
    int tid = threadIdx.x;
    int v = (tid < nblk) ? g_blockSums[tid] : 0;
    s[tid] = v;
    __syncthreads();
#pragma unroll
    for (int off = 1; off < SCAN_B; off <<= 1) {
        int a = (tid >= off) ? s[tid - off] : 0;
        __syncthreads();
        s[tid] += a;
        __syncthreads();
    }
    if (tid < nblk) g_blockSums[tid] = s[tid] - v;     // exclusive block offsets
}

__global__ void k_scan3() {
    int i = blockIdx.x * blockDim.x + threadIdx.x;
    if (i < N_NODES) {
        int e = g_offs[i] + g_blockSums[i >> 10];
        g_offs[i] = e;
        g_cursor[i] = e;
        if (i == N_NODES - 1) g_offs[N_NODES] = e + g_deg[i];
    }
}

// ---------------- CSR fill ----------------
__global__ void k_fill(const int* __restrict__ ei, int E) {
    for (int e = blockIdx.x * blockDim.x + threadIdx.x; e < E;
         e += gridDim.x * blockDim.x) {
        int s = ei[e];
        int d = ei[E + e];
        int pos = atomicAdd(&g_cursor[d], 1);
        g_csr_src[pos] = s;
        g_csr_w[pos] = g_dis[s] * g_dis[d];
    }
}

__global__ void k_fill_loops() {
    int i = blockIdx.x * blockDim.x + threadIdx.x;
    if (i < N_NODES) {
        int pos = atomicAdd(&g_cursor[i], 1);
        g_csr_src[pos] = i;
        float d = g_dis[i];
        g_csr_w[pos] = d * d;
    }
}

// ---------------- GEMM: g_bufT[M,256] = A[M,256] * B[256,256] ----------------
// BM=128, BN=128, BK=16, 256 threads, 8x8 per-thread tile.
__global__ __launch_bounds__(256) void k_gemm256(const float* __restrict__ A,
                                                 const float* __restrict__ B,
                                                 int M) {
    const float* Ap = A ? A : g_bufH;   // layer 2 reads g_bufH
    __shared__ float As[16][128];
    __shared__ float Bs[16][128];
    int tid = threadIdx.x;
    int tx = tid & 15;        // 0..15 -> col
    int ty = tid >> 4;        // 0..15 -> row
    int rowBase = blockIdx.x * 128;
    int colBase = blockIdx.y * 128;

    float acc[8][8];
#pragma unroll
    for (int i = 0; i < 8; i++)
#pragma unroll
        for (int j = 0; j < 8; j++) acc[i][j] = 0.f;

    for (int k0 = 0; k0 < 256; k0 += 16) {
        // A tile: 128 rows x 16 cols = 512 float4, 2 per thread. Store transposed.
#pragma unroll
        for (int j = 0; j < 2; j++) {
            int idx = tid + j * 256;
            int r = idx >> 2, c4 = idx & 3;
            int grow = rowBase + r;
            float4 v = make_float4(0.f, 0.f, 0.f, 0.f);
            if (grow < M)
                v = *(const float4*)(Ap + (size_t)grow * 256 + k0 + c4 * 4);
            As[c4 * 4 + 0][r] = v.x;
            As[c4 * 4 + 1][r] = v.y;
            As[c4 * 4 + 2][r] = v.z;
            As[c4 * 4 + 3][r] = v.w;
        }
        // B tile: 16 rows x 128 cols = 512 float4, 2 per thread.
#pragma unroll
        for (int j = 0; j < 2; j++) {
            int idx = tid + j * 256;
            int r = idx >> 5, c4 = idx & 31;
            float4 v = *(const float4*)(B + (size_t)(k0 + r) * 256 + colBase + c4 * 4);
            *(float4*)&Bs[r][c4 * 4] = v;
        }
        __syncthreads();
#pragma unroll
        for (int k = 0; k < 16; k++) {
            float a[8], b[8];
#pragma unroll
            for (int i = 0; i < 8; i++) a[i] = As[k][ty * 8 + i];
#pragma unroll
            for (int i = 0; i < 8; i++) b[i] = Bs[k][tx * 8 + i];
#pragma unroll
            for (int i = 0; i < 8; i++)
#pragma unroll
                for (int j = 0; j < 8; j++) acc[i][j] += a[i] * b[j];
        }
        __syncthreads();
    }
#pragma unroll
    for (int i = 0; i < 8; i++) {
        int grow = rowBase + ty * 8 + i;
        if (grow < M) {
            float* cp = g_bufT + (size_t)grow * 256 + colBase + tx * 8;
            *(float4*)cp = make_float4(acc[i][0], acc[i][1], acc[i][2], acc[i][3]);
            *(float4*)(cp + 4) = make_float4(acc[i][4], acc[i][5], acc[i][6], acc[i][7]);
        }
    }
}

// ---------------- aggregation (warp per node): g_bufH = relu(agg(g_bufT) + bias) ----
__global__ __launch_bounds__(256) void k_agg_relu(const float* __restrict__ bias) {
    int w = (blockIdx.x * blockDim.x + threadIdx.x) >> 5;
    int lane = threadIdx.x & 31;
    if (w >= N_NODES) return;
    int beg = g_offs[w], end = g_offs[w + 1];
    float4 a0 = make_float4(0.f, 0.f, 0.f, 0.f);
    float4 a1 = a0;
    for (int e = beg; e < end; e++) {
        int s = g_csr_src[e];
        float wt = g_csr_w[e];
        const float4* r = (const float4*)(g_bufT + (size_t)s * 256);
        float4 v0 = r[lane];
        float4 v1 = r[lane + 32];
        a0.x += wt * v0.x; a0.y += wt * v0.y; a0.z += wt * v0.z; a0.w += wt * v0.w;
        a1.x += wt * v1.x; a1.y += wt * v1.y; a1.z += wt * v1.z; a1.w += wt * v1.w;
    }
    const float4* bv = (const float4*)bias;
    float4 b0 = bv[lane], b1 = bv[lane + 32];
    a0.x = fmaxf(a0.x + b0.x, 0.f); a0.y = fmaxf(a0.y + b0.y, 0.f);
    a0.z = fmaxf(a0.z + b0.z, 0.f); a0.w = fmaxf(a0.w + b0.w, 0.f);
    a1.x = fmaxf(a1.x + b1.x, 0.f); a1.y = fmaxf(a1.y + b1.y, 0.f);
    a1.z = fmaxf(a1.z + b1.z, 0.f); a1.w = fmaxf(a1.w + b1.w, 0.f);
    float4* out = (float4*)(g_bufH + (size_t)w * 256);
    out[lane] = a0;
    out[lane + 32] = a1;
}

// ---------------- agg layer 2 fused with final linear: out[i] = relu(agg+b2) @ Wl + bl
__global__ __launch_bounds__(256) void k_agg_final(const float* __restrict__ b2,
                                                   const float* __restrict__ Wl,
                                                   const float* __restrict__ bl,
                                                   float* __restrict__ out) {
    int w = (blockIdx.x * blockDim.x + threadIdx.x) >> 5;
    int lane = threadIdx.x & 31;
    if (w >= N_NODES) return;
    int beg = g_offs[w], end = g_offs[w + 1];
    float4 a0 = make_float4(0.f, 0.f, 0.f, 0.f);
    float4 a1 = a0;
    for (int e = beg; e < end; e++) {
        int s = g_csr_src[e];
        float wt = g_csr_w[e];
        const float4* r = (const float4*)(g_bufT + (size_t)s * 256);
        float4 v0 = r[lane];
        float4 v1 = r[lane + 32];
        a0.x += wt * v0.x; a0.y += wt * v0.y; a0.z += wt * v0.z; a0.w += wt * v0.w;
        a1.x += wt * v1.x; a1.y += wt * v1.y; a1.z += wt * v1.z; a1.w += wt * v1.w;
    }
    const float4* bv = (const float4*)b2;
    const float4* wv = (const float4*)Wl;
    float4 b0 = bv[lane], b1 = bv[lane + 32];
    float4 w0 = wv[lane], w1 = wv[lane + 32];
    float s =
        fmaxf(a0.x + b0.x, 0.f) * w0.x + fmaxf(a0.y + b0.y, 0.f) * w0.y +
        fmaxf(a0.z + b0.z, 0.f) * w0.z + fmaxf(a0.w + b0.w, 0.f) * w0.w +
        fmaxf(a1.x + b1.x, 0.f) * w1.x + fmaxf(a1.y + b1.y, 0.f) * w1.y +
        fmaxf(a1.z + b1.z, 0.f) * w1.z + fmaxf(a1.w + b1.w, 0.f) * w1.w;
#pragma unroll
    for (int o = 16; o > 0; o >>= 1) s += __shfl_xor_sync(0xFFFFFFFFu, s, o);
    if (lane == 0) out[w] = s + bl[0];
}

// ---------------- launch ----------------
extern "C" void kernel_launch(void* const* d_in, const int* in_sizes, int n_in,
                              void* d_out, int out_size) {
    const float* x  = (const float*)d_in[0];
    const int*   ei = (const int*)d_in[1];     // edge_index is int32 (JAX x64 disabled)
    const float* W1 = (const float*)d_in[2];
    const float* b1 = (const float*)d_in[3];
    const float* W2 = (const float*)d_in[4];
    const float* b2 = (const float*)d_in[5];
    const float* Wl = (const float*)d_in[6];
    const float* bl = (const float*)d_in[7];
    float* out = (float*)d_out;

    int E = in_sizes[1] / 2;
    int nblk = (N_NODES + SCAN_B - 1) / SCAN_B;           // 98
    int node_blocks = (N_NODES + 255) / 256;              // 391 blocks for node loops
    int agg_blocks = (N_NODES * 32 + 255) / 256;          // 12500 (warp per node)

    // CSR build (shared by both conv layers)
    k_deg_init<<<node_blocks, 256>>>();
    k_hist<<<4096, 256>>>(ei, E);
    k_dis<<<node_blocks, 256>>>();
    k_scan1<<<nblk, SCAN_B>>>();
    k_scan2<<<1, SCAN_B>>>(nblk);
    k_scan3<<<node_blocks, 256>>>();
    k_fill<<<4096, 256>>>(ei, E);
    k_fill_loops<<<node_blocks, 256>>>();

    dim3 ggrid((N_NODES + 127) / 128, 2);

    // layer 1: T = x @ W1 ; H = relu(agg(T) + b1)
    k_gemm256<<<ggrid, 256>>>(x, W1, N_NODES);
    k_agg_relu<<<agg_blocks, 256>>>(b1);

    // layer 2: T = H @ W2 ; out = relu(agg(T) + b2) @ Wl + bl   (fused)
    k_gemm256<<<ggrid, 256>>>(nullptr, W2, N_NODES);
    k_agg_final<<<agg_blocks, 256>>>(b2, Wl, bl, out);
}

// round 4
// speedup vs baseline: 1.0017x; 1.0017x over previous
#include <cuda_runtime.h>
#include <cuda_bf16.h>
#include <cstdint>

#define N_NODES 100000
#define C_DIM   256
#define CSR_CAP 3400000
#define SCAN_B  1024

// ---------------- device scratch (no allocations allowed) ----------------
__device__ int   g_deg[N_NODES];
__device__ int   g_offs[N_NODES + 1];
__device__ int   g_cursor[N_NODES];
__device__ float g_dis[N_NODES];
__device__ int   g_blockSums[SCAN_B];
__device__ int   g_csr_src[CSR_CAP];
__device__ float g_csr_w[CSR_CAP];
__device__ float g_bufT[(size_t)N_NODES * C_DIM];   // transformed features (X@W)
__device__ float g_bufH[(size_t)N_NODES * C_DIM];   // aggregated+activated features

// ---------------- degree / normalization ----------------
__global__ void k_deg_init() {
    int i = blockIdx.x * blockDim.x + threadIdx.x;
    if (i < N_NODES) g_deg[i] = 1;   // self-loop
}

__global__ void k_hist(const int* __restrict__ ei, int E) {
    for (int e = blockIdx.x * blockDim.x + threadIdx.x; e < E;
         e += gridDim.x * blockDim.x) {
        atomicAdd(&g_deg[ei[E + e]], 1);   // dst row
    }
}

__global__ void k_dis() {
    int i = blockIdx.x * blockDim.x + threadIdx.x;
    if (i < N_NODES) g_dis[i] = rsqrtf((float)g_deg[i]);
}

// ---------------- exclusive scan of degrees -> CSR row offsets ----------------
__global__ void k_scan1() {
    __shared__ int s[SCAN_B];
    int tid = threadIdx.x;
    int i = blockIdx.x * SCAN_B + tid;
    int v = (i < N_NODES) ? g_deg[i] : 0;
    s[tid] = v;
    __syncthreads();
#pragma unroll
    for (int off = 1; off < SCAN_B; off <<= 1) {
        int a = (tid >= off) ? s[tid - off] : 0;
        __syncthreads();
        s[tid] += a;
        __syncthreads();
    }
    if (i < N_NODES) g_offs[i] = s[tid] - v;          // block-local exclusive
    if (tid == SCAN_B - 1) g_blockSums[blockIdx.x] = s[tid];
}

__global__ void k_scan2(int nblk) {
    __shared__ int s[SCAN_B];
    int tid = threadIdx.x;
    int v = (tid < nblk) ? g_blockSums[tid] : 0;
    s[tid] = v;
    __syncthreads();
#pragma unroll
    for (int off = 1; off < SCAN_B; off <<= 1) {
        int a = (tid >= off) ? s[tid - off] : 0;
        __syncthreads();
        s[tid] += a;
        __syncthreads();
    }
    if (tid < nblk) g_blockSums[tid] = s[tid] - v;     // exclusive block offsets
}

__global__ void k_scan3() {
    int i = blockIdx.x * blockDim.x + threadIdx.x;
    if (i < N_NODES) {
        int e = g_offs[i] + g_blockSums[i >> 10];
        g_offs[i] = e;
        g_cursor[i] = e;
        if (i == N_NODES - 1) g_offs[N_NODES] = e + g_deg[i];
    }
}

// ---------------- CSR fill ----------------
__global__ void k_fill(const int* __restrict__ ei, int E) {
    for (int e = blockIdx.x * blockDim.x + threadIdx.x; e < E;
         e += gridDim.x * blockDim.x) {
        int s = ei[e];
        int d = ei[E + e];
        int pos = atomicAdd(&g_cursor[d], 1);
        g_csr_src[pos] = s;
        g_csr_w[pos] = g_dis[s] * g_dis[d];
    }
}

__global__ void k_fill_loops() {
    int i = blockIdx.x * blockDim.x + threadIdx.x;
    if (i < N_NODES) {
        int pos = atomicAdd(&g_cursor[i], 1);
        g_csr_src[pos] = i;
        float d = g_dis[i];
        g_csr_w[pos] = d * d;
    }
}

// ---------------- GEMM: g_bufT[M,256] = A[M,256] * B[256,256] ----------------
// BM=128, BN=128, BK=16, 256 threads, 8x8 per-thread tile.
__global__ __launch_bounds__(256) void k_gemm256(const float* __restrict__ A,
                                                 const float* __restrict__ B,
                                                 int M) {
    const float* Ap = A ? A : g_bufH;   // layer 2 reads g_bufH
    __shared__ float As[16][128];
    __shared__ float Bs[16][128];
    int tid = threadIdx.x;
    int tx = tid & 15;        // 0..15 -> col
    int ty = tid >> 4;        // 0..15 -> row
    int rowBase = blockIdx.x * 128;
    int colBase = blockIdx.y * 128;

    float acc[8][8];
#pragma unroll
    for (int i = 0; i < 8; i++)
#pragma unroll
        for (int j = 0; j < 8; j++) acc[i][j] = 0.f;

    for (int k0 = 0; k0 < 256; k0 += 16) {
        // A tile: 128 rows x 16 cols = 512 float4, 2 per thread. Store transposed.
#pragma unroll
        for (int j = 0; j < 2; j++) {
            int idx = tid + j * 256;
            int r = idx >> 2, c4 = idx & 3;
            int grow = rowBase + r;
            float4 v = make_float4(0.f, 0.f, 0.f, 0.f);
            if (grow < M)
                v = *(const float4*)(Ap + (size_t)grow * 256 + k0 + c4 * 4);
            As[c4 * 4 + 0][r] = v.x;
            As[c4 * 4 + 1][r] = v.y;
            As[c4 * 4 + 2][r] = v.z;
            As[c4 * 4 + 3][r] = v.w;
        }
        // B tile: 16 rows x 128 cols = 512 float4, 2 per thread.
#pragma unroll
        for (int j = 0; j < 2; j++) {
            int idx = tid + j * 256;
            int r = idx >> 5, c4 = idx & 31;
            float4 v = *(const float4*)(B + (size_t)(k0 + r) * 256 + colBase + c4 * 4);
            *(float4*)&Bs[r][c4 * 4] = v;
        }
        __syncthreads();
#pragma unroll
        for (int k = 0; k < 16; k++) {
            float a[8], b[8];
#pragma unroll
            for (int i = 0; i < 8; i++) a[i] = As[k][ty * 8 + i];
#pragma unroll
            for (int i = 0; i < 8; i++) b[i] = Bs[k][tx * 8 + i];
#pragma unroll
            for (int i = 0; i < 8; i++)
#pragma unroll
                for (int j = 0; j < 8; j++) acc[i][j] += a[i] * b[j];
        }
        __syncthreads();
    }
#pragma unroll
    for (int i = 0; i < 8; i++) {
        int grow = rowBase + ty * 8 + i;
        if (grow < M) {
            float* cp = g_bufT + (size_t)grow * 256 + colBase + tx * 8;
            *(float4*)cp = make_float4(acc[i][0], acc[i][1], acc[i][2], acc[i][3]);
            *(float4*)(cp + 4) = make_float4(acc[i][4], acc[i][5], acc[i][6], acc[i][7]);
        }
    }
}

// ---------------- aggregation (warp per node): g_bufH = relu(agg(g_bufT) + bias) ----
__global__ __launch_bounds__(256) void k_agg_relu(const float* __restrict__ bias) {
    int w = (blockIdx.x * blockDim.x + threadIdx.x) >> 5;
    int lane = threadIdx.x & 31;
    if (w >= N_NODES) return;
    int beg = g_offs[w], end = g_offs[w + 1];
    float4 a0 = make_float4(0.f, 0.f, 0.f, 0.f);
    float4 a1 = a0;
    for (int e = beg; e < end; e++) {
        int s = g_csr_src[e];
        float wt = g_csr_w[e];
        const float4* r = (const float4*)(g_bufT + (size_t)s * 256);
        float4 v0 = r[lane];
        float4 v1 = r[lane + 32];
        a0.x += wt * v0.x; a0.y += wt * v0.y; a0.z += wt * v0.z; a0.w += wt * v0.w;
        a1.x += wt * v1.x; a1.y += wt * v1.y; a1.z += wt * v1.z; a1.w += wt * v1.w;
    }
    const float4* bv = (const float4*)bias;
    float4 b0 = bv[lane], b1 = bv[lane + 32];
    a0.x = fmaxf(a0.x + b0.x, 0.f); a0.y = fmaxf(a0.y + b0.y, 0.f);
    a0.z = fmaxf(a0.z + b0.z, 0.f); a0.w = fmaxf(a0.w + b0.w, 0.f);
    a1.x = fmaxf(a1.x + b1.x, 0.f); a1.y = fmaxf(a1.y + b1.y, 0.f);
    a1.z = fmaxf(a1.z + b1.z, 0.f); a1.w = fmaxf(a1.w + b1.w, 0.f);
    float4* out = (float4*)(g_bufH + (size_t)w * 256);
    out[lane] = a0;
    out[lane + 32] = a1;
}

// ---------------- agg layer 2 fused with final linear: out[i] = relu(agg+b2) @ Wl + bl
__global__ __launch_bounds__(256) void k_agg_final(const float* __restrict__ b2,
                                                   const float* __restrict__ Wl,
                                                   const float* __restrict__ bl,
                                                   float* __restrict__ out) {
    int w = (blockIdx.x * blockDim.x + threadIdx.x) >> 5;
    int lane = threadIdx.x & 31;
    if (w >= N_NODES) return;
    int beg = g_offs[w], end = g_offs[w + 1];
    float4 a0 = make_float4(0.f, 0.f, 0.f, 0.f);
    float4 a1 = a0;
    for (int e = beg; e < end; e++) {
        int s = g_csr_src[e];
        float wt = g_csr_w[e];
        const float4* r = (const float4*)(g_bufT + (size_t)s * 256);
        float4 v0 = r[lane];
        float4 v1 = r[lane + 32];
        a0.x += wt * v0.x; a0.y += wt * v0.y; a0.z += wt * v0.z; a0.w += wt * v0.w;
        a1.x += wt * v1.x; a1.y += wt * v1.y; a1.z += wt * v1.z; a1.w += wt * v1.w;
    }
    const float4* bv = (const float4*)b2;
    const float4* wv = (const float4*)Wl;
    float4 b0 = bv[lane], b1 = bv[lane + 32];
    float4 w0 = wv[lane], w1 = wv[lane + 32];
    float s =
        fmaxf(a0.x + b0.x, 0.f) * w0.x + fmaxf(a0.y + b0.y, 0.f) * w0.y +
        fmaxf(a0.z + b0.z, 0.f) * w0.z + fmaxf(a0.w + b0.w, 0.f) * w0.w +
        fmaxf(a1.x + b1.x, 0.f) * w1.x + fmaxf(a1.y + b1.y, 0.f) * w1.y +
        fmaxf(a1.z + b1.z, 0.f) * w1.z + fmaxf(a1.w + b1.w, 0.f) * w1.w;
#pragma unroll
    for (int o = 16; o > 0; o >>= 1) s += __shfl_xor_sync(0xFFFFFFFFu, s, o);
    if (lane == 0) out[w] = s + bl[0];
}

// ---------------- launch ----------------
extern "C" void kernel_launch(void* const* d_in, const int* in_sizes, int n_in,
                              void* d_out, int out_size) {
    const float* x  = (const float*)d_in[0];
    const int*   ei = (const int*)d_in[1];     // edge_index is int32 (JAX x64 disabled)
    const float* W1 = (const float*)d_in[2];
    const float* b1 = (const float*)d_in[3];
    const float* W2 = (const float*)d_in[4];
    const float* b2 = (const float*)d_in[5];
    const float* Wl = (const float*)d_in[6];
    const float* bl = (const float*)d_in[7];
    float* out = (float*)d_out;

    int E = in_sizes[1] / 2;
    int nblk = (N_NODES + SCAN_B - 1) / SCAN_B;           // 98
    int node_blocks = (N_NODES + 255) / 256;              // 391 blocks for node loops
    int agg_blocks = (N_NODES * 32 + 255) / 256;          // 12500 (warp per node)

    // CSR build (shared by both conv layers)
    k_deg_init<<<node_blocks, 256>>>();
    k_hist<<<4096, 256>>>(ei, E);
    k_dis<<<node_blocks, 256>>>();
    k_scan1<<<nblk, SCAN_B>>>();
    k_scan2<<<1, SCAN_B>>>(nblk);
    k_scan3<<<node_blocks, 256>>>();
    k_fill<<<4096, 256>>>(ei, E);
    k_fill_loops<<<node_blocks, 256>>>();

    dim3 ggrid((N_NODES + 127) / 128, 2);

    // layer 1: T = x @ W1 ; H = relu(agg(T) + b1)
    k_gemm256<<<ggrid, 256>>>(x, W1, N_NODES);
    k_agg_relu<<<agg_blocks, 256>>>(b1);

    // layer 2: T = H @ W2 ; out = relu(agg(T) + b2) @ Wl + bl   (fused)
    k_gemm256<<<ggrid, 256>>>(nullptr, W2, N_NODES);
    k_agg_final<<<agg_blocks, 256>>>(b2, Wl, bl, out);
}

// round 5
// speedup vs baseline: 1.3822x; 1.3800x over previous
#include <cuda_runtime.h>
#include <cuda_bf16.h>
#include <cstdint>

#define N_NODES 100000
#define C_DIM   256
#define CSR_CAP 3400000
#define SCAN_B  1024

// GEMM tiling
#define BM 128
#define BN 128
#define BK 32
#define AS_STRIDE 129   // [k][m] floats, odd stride -> conflict-free transposed stores
#define BS_STRIDE 132   // [k][n] floats, float4-aligned rows

// ---------------- device scratch (no allocations allowed) ----------------
__device__ int   g_deg[N_NODES];
__device__ int   g_offs[N_NODES + 1];
__device__ int   g_cursor[N_NODES];
__device__ float g_dis[N_NODES];
__device__ int   g_blockSums[SCAN_B];
__device__ int   g_csr_src[CSR_CAP];
__device__ float g_csr_w[CSR_CAP];
__device__ float g_bufT[(size_t)N_NODES * C_DIM];   // transformed features (X@W)
__device__ float g_bufH[(size_t)N_NODES * C_DIM];   // aggregated+activated features

// ---------------- degree / normalization ----------------
__global__ void k_deg_init() {
    int i = blockIdx.x * blockDim.x + threadIdx.x;
    if (i < N_NODES) g_deg[i] = 1;   // self-loop
}

__global__ void k_hist(const int* __restrict__ ei, int E) {
    for (int e = blockIdx.x * blockDim.x + threadIdx.x; e < E;
         e += gridDim.x * blockDim.x) {
        atomicAdd(&g_deg[ei[E + e]], 1);   // dst row
    }
}

// ---------------- exclusive scan of degrees -> CSR row offsets ----------------
__global__ void k_scan1() {
    __shared__ int s[SCAN_B];
    int tid = threadIdx.x;
    int i = blockIdx.x * SCAN_B + tid;
    int v = (i < N_NODES) ? g_deg[i] : 0;
    s[tid] = v;
    __syncthreads();
#pragma unroll
    for (int off = 1; off < SCAN_B; off <<= 1) {
        int a = (tid >= off) ? s[tid - off] : 0;
        __syncthreads();
        s[tid] += a;
        __syncthreads();
    }
    if (i < N_NODES) g_offs[i] = s[tid] - v;          // block-local exclusive
    if (tid == SCAN_B - 1) g_blockSums[blockIdx.x] = s[tid];
}

__global__ void k_scan2(int nblk) {
    __shared__ int s[SCAN_B];
    int tid = threadIdx.x;
    int v = (tid < nblk) ? g_blockSums[tid] : 0;
    s[tid] = v;
    __syncthreads();
#pragma unroll
    for (int off = 1; off < SCAN_B; off <<= 1) {
        int a = (tid >= off) ? s[tid - off] : 0;
        __syncthreads();
        s[tid] += a;
        __syncthreads();
    }
    if (tid < nblk) g_blockSums[tid] = s[tid] - v;     // exclusive block offsets
}

// scan finalize + deg_inv_sqrt + deterministic self-loop in each row's LAST slot
// (k_fill atomically fills slots offs[i]..offs[i]+deg-2 with incoming edges;
//  slot offs[i]+deg-1 is reserved for the self-loop -> no atomic, no overlap)
__global__ void k_scan3() {
    int i = blockIdx.x * blockDim.x + threadIdx.x;
    if (i < N_NODES) {
        int deg = g_deg[i];
        int e = g_offs[i] + g_blockSums[i >> 10];
        g_offs[i] = e;
        g_cursor[i] = e;
        float dis = rsqrtf((float)deg);
        g_dis[i] = dis;
        g_csr_src[e + deg - 1] = i;
        g_csr_w[e + deg - 1] = dis * dis;
        if (i == N_NODES - 1) g_offs[N_NODES] = e + deg;
    }
}

// ---------------- CSR fill ----------------
__global__ void k_fill(const int* __restrict__ ei, int E) {
    for (int e = blockIdx.x * blockDim.x + threadIdx.x; e < E;
         e += gridDim.x * blockDim.x) {
        int s = ei[e];
        int d = ei[E + e];
        int pos = atomicAdd(&g_cursor[d], 1);
        g_csr_src[pos] = s;
        g_csr_w[pos] = g_dis[s] * g_dis[d];
    }
}

// ---------------- tf32 tensor-core GEMM: g_bufT[M,256] = A[M,256] * B[256,256] ----
__device__ __forceinline__ uint32_t f2tf32(float f) {
    uint32_t u;
    asm("cvt.rna.tf32.f32 %0, %1;" : "=r"(u) : "f"(f));
    return u;
}

__device__ __forceinline__ void mma_tf32(float c[4], const uint32_t a[4],
                                         const uint32_t b[2]) {
    asm volatile(
        "mma.sync.aligned.m16n8k8.row.col.f32.tf32.tf32.f32 "
        "{%0,%1,%2,%3}, {%4,%5,%6,%7}, {%8,%9}, {%0,%1,%2,%3};"
        : "+f"(c[0]), "+f"(c[1]), "+f"(c[2]), "+f"(c[3])
        : "r"(a[0]), "r"(a[1]), "r"(a[2]), "r"(a[3]), "r"(b[0]), "r"(b[1]));
}

// 256 threads; 8 warps as 4(M) x 2(N); warp tile 32x64; mma m16n8k8.
__global__ __launch_bounds__(256, 2) void k_gemm_tf32(const float* __restrict__ A,
                                                      const float* __restrict__ Bw,
                                                      int M) {
    const float* Ap = A ? A : g_bufH;   // layer 2 reads g_bufH
    __shared__ uint32_t As[BK * AS_STRIDE];   // [k][m] tf32 bits
    __shared__ uint32_t Bs[BK * BS_STRIDE];   // [k][n] tf32 bits

    int tid = threadIdx.x;
    int lane = tid & 31;
    int warp = tid >> 5;
    int warpM = warp & 3;          // 0..3 -> 32 rows each
    int warpN = warp >> 2;         // 0..1 -> 64 cols each
    int rowBase = blockIdx.x * BM;
    int colBase = blockIdx.y * BN;

    int r = lane >> 2;             // 0..7
    int cq = lane & 3;             // 0..3

    float c[2][8][4];
#pragma unroll
    for (int mt = 0; mt < 2; mt++)
#pragma unroll
        for (int nt = 0; nt < 8; nt++)
#pragma unroll
            for (int j = 0; j < 4; j++) c[mt][nt][j] = 0.f;

    for (int k0 = 0; k0 < 256; k0 += BK) {
        // A tile: 128 rows x 32 k -> id over (m, k4): k4 = id&7 (coalesced), m = id>>3
#pragma unroll
        for (int it = 0; it < 4; it++) {
            int id = tid + it * 256;
            int k4 = id & 7;
            int m = id >> 3;
            int grow = rowBase + m;
            float4 v = make_float4(0.f, 0.f, 0.f, 0.f);
            if (grow < M)
                v = *(const float4*)(Ap + (size_t)grow * 256 + k0 + k4 * 4);
            As[(k4 * 4 + 0) * AS_STRIDE + m] = f2tf32(v.x);
            As[(k4 * 4 + 1) * AS_STRIDE + m] = f2tf32(v.y);
            As[(k4 * 4 + 2) * AS_STRIDE + m] = f2tf32(v.z);
            As[(k4 * 4 + 3) * AS_STRIDE + m] = f2tf32(v.w);
        }
        // B tile: 32 k x 128 n -> id over (k, n4): n4 = id&31 (coalesced), k = id>>5
#pragma unroll
        for (int it = 0; it < 4; it++) {
            int id = tid + it * 256;
            int n4 = id & 31;
            int k = id >> 5;
            float4 v = *(const float4*)(Bw + (size_t)(k0 + k) * 256 + colBase + n4 * 4);
            uint4 t;
            t.x = f2tf32(v.x); t.y = f2tf32(v.y); t.z = f2tf32(v.z); t.w = f2tf32(v.w);
            *(uint4*)&Bs[k * BS_STRIDE + n4 * 4] = t;
        }
        __syncthreads();

#pragma unroll
        for (int kk = 0; kk < BK; kk += 8) {
            uint32_t a[2][4], b[8][2];
#pragma unroll
            for (int mt = 0; mt < 2; mt++) {
                int m = warpM * 32 + mt * 16 + r;
                a[mt][0] = As[(kk + cq) * AS_STRIDE + m];
                a[mt][1] = As[(kk + cq) * AS_STRIDE + m + 8];
                a[mt][2] = As[(kk + cq + 4) * AS_STRIDE + m];
                a[mt][3] = As[(kk + cq + 4) * AS_STRIDE + m + 8];
            }
#pragma unroll
            for (int nt = 0; nt < 8; nt++) {
                int n = warpN * 64 + nt * 8 + r;
                b[nt][0] = Bs[(kk + cq) * BS_STRIDE + n];
                b[nt][1] = Bs[(kk + cq + 4) * BS_STRIDE + n];
            }
#pragma unroll
            for (int mt = 0; mt < 2; mt++)
#pragma unroll
                for (int nt = 0; nt < 8; nt++) mma_tf32(c[mt][nt], a[mt], b[nt]);
        }
        __syncthreads();
    }

    // epilogue: c0,c1 -> (row, col..col+1); c2,c3 -> (row+8, col..col+1)
#pragma unroll
    for (int mt = 0; mt < 2; mt++) {
        int grow = rowBase + warpM * 32 + mt * 16 + r;
#pragma unroll
        for (int nt = 0; nt < 8; nt++) {
            int gcol = colBase + warpN * 64 + nt * 8 + cq * 2;
            if (grow < M)
                *(float2*)(g_bufT + (size_t)grow * 256 + gcol) =
                    make_float2(c[mt][nt][0], c[mt][nt][1]);
            if (grow + 8 < M)
                *(float2*)(g_bufT + (size_t)(grow + 8) * 256 + gcol) =
                    make_float2(c[mt][nt][2], c[mt][nt][3]);
        }
    }
}

// ---------------- aggregation (warp per node): g_bufH = relu(agg(g_bufT) + bias) ----
__global__ __launch_bounds__(256) void k_agg_relu(const float* __restrict__ bias) {
    int w = (blockIdx.x * blockDim.x + threadIdx.x) >> 5;
    int lane = threadIdx.x & 31;
    if (w >= N_NODES) return;
    int beg = g_offs[w], end = g_offs[w + 1];
    float4 a0 = make_float4(0.f, 0.f, 0.f, 0.f);
    float4 a1 = a0;
    for (int e = beg; e < end; e++) {
        int s = g_csr_src[e];
        float wt = g_csr_w[e];
        const float4* r = (const float4*)(g_bufT + (size_t)s * 256);
        float4 v0 = r[lane];
        float4 v1 = r[lane + 32];
        a0.x += wt * v0.x; a0.y += wt * v0.y; a0.z += wt * v0.z; a0.w += wt * v0.w;
        a1.x += wt * v1.x; a1.y += wt * v1.y; a1.z += wt * v1.z; a1.w += wt * v1.w;
    }
    const float4* bv = (const float4*)bias;
    float4 b0 = bv[lane], b1 = bv[lane + 32];
    a0.x = fmaxf(a0.x + b0.x, 0.f); a0.y = fmaxf(a0.y + b0.y, 0.f);
    a0.z = fmaxf(a0.z + b0.z, 0.f); a0.w = fmaxf(a0.w + b0.w, 0.f);
    a1.x = fmaxf(a1.x + b1.x, 0.f); a1.y = fmaxf(a1.y + b1.y, 0.f);
    a1.z = fmaxf(a1.z + b1.z, 0.f); a1.w = fmaxf(a1.w + b1.w, 0.f);
    float4* out = (float4*)(g_bufH + (size_t)w * 256);
    out[lane] = a0;
    out[lane + 32] = a1;
}

// ---------------- agg layer 2 fused with final linear: out[i] = relu(agg+b2) @ Wl + bl
__global__ __launch_bounds__(256) void k_agg_final(const float* __restrict__ b2,
                                                   const float* __restrict__ Wl,
                                                   const float* __restrict__ bl,
                                                   float* __restrict__ out) {
    int w = (blockIdx.x * blockDim.x + threadIdx.x) >> 5;
    int lane = threadIdx.x & 31;
    if (w >= N_NODES) return;
    int beg = g_offs[w], end = g_offs[w + 1];
    float4 a0 = make_float4(0.f, 0.f, 0.f, 0.f);
    float4 a1 = a0;
    for (int e = beg; e < end; e++) {
        int s = g_csr_src[e];
        float wt = g_csr_w[e];
        const float4* r = (const float4*)(g_bufT + (size_t)s * 256);
        float4 v0 = r[lane];
        float4 v1 = r[lane + 32];
        a0.x += wt * v0.x; a0.y += wt * v0.y; a0.z += wt * v0.z; a0.w += wt * v0.w;
        a1.x += wt * v1.x; a1.y += wt * v1.y; a1.z += wt * v1.z; a1.w += wt * v1.w;
    }
    const float4* bv = (const float4*)b2;
    const float4* wv = (const float4*)Wl;
    float4 b0 = bv[lane], b1 = bv[lane + 32];
    float4 w0 = wv[lane], w1 = wv[lane + 32];
    float s =
        fmaxf(a0.x + b0.x, 0.f) * w0.x + fmaxf(a0.y + b0.y, 0.f) * w0.y +
        fmaxf(a0.z + b0.z, 0.f) * w0.z + fmaxf(a0.w + b0.w, 0.f) * w0.w +
        fmaxf(a1.x + b1.x, 0.f) * w1.x + fmaxf(a1.y + b1.y, 0.f) * w1.y +
        fmaxf(a1.z + b1.z, 0.f) * w1.z + fmaxf(a1.w + b1.w, 0.f) * w1.w;
#pragma unroll
    for (int o = 16; o > 0; o >>= 1) s += __shfl_xor_sync(0xFFFFFFFFu, s, o);
    if (lane == 0) out[w] = s + bl[0];
}

// ---------------- launch ----------------
extern "C" void kernel_launch(void* const* d_in, const int* in_sizes, int n_in,
                              void* d_out, int out_size) {
    const float* x  = (const float*)d_in[0];
    const int*   ei = (const int*)d_in[1];     // edge_index is int32 (JAX x64 disabled)
    const float* W1 = (const float*)d_in[2];
    const float* b1 = (const float*)d_in[3];
    const float* W2 = (const float*)d_in[4];
    const float* b2 = (const float*)d_in[5];
    const float* Wl = (const float*)d_in[6];
    const float* bl = (const float*)d_in[7];
    float* out = (float*)d_out;

    int E = in_sizes[1] / 2;
    int nblk = (N_NODES + SCAN_B - 1) / SCAN_B;           // 98
    int node_blocks = (N_NODES + 255) / 256;              // 391
    int agg_blocks = (N_NODES * 32 + 255) / 256;          // 12500 (warp per node)

    // CSR build (shared by both conv layers)
    k_deg_init<<<node_blocks, 256>>>();
    k_hist<<<4096, 256>>>(ei, E);
    k_scan1<<<nblk, SCAN_B>>>();
    k_scan2<<<1, SCAN_B>>>(nblk);
    k_scan3<<<node_blocks, 256>>>();     // offsets + dis + self-loops
    k_fill<<<4096, 256>>>(ei, E);

    dim3 ggrid((N_NODES + BM - 1) / BM, 256 / BN);        // (782, 2)

    // layer 1: T = x @ W1 ; H = relu(agg(T) + b1)
    k_gemm_tf32<<<ggrid, 256>>>(x, W1, N_NODES);
    k_agg_relu<<<agg_blocks, 256>>>(b1);

    // layer 2: T = H @ W2 ; out = relu(agg(T) + b2) @ Wl + bl   (fused)
    k_gemm_tf32<<<ggrid, 256>>>(nullptr, W2, N_NODES);
    k_agg_final<<<agg_blocks, 256>>>(b2, Wl, bl, out);
}

// round 6
// speedup vs baseline: 1.8412x; 1.3320x over previous
#include <cuda_runtime.h>
#include <cuda_fp16.h>
#include <cuda_bf16.h>
#include <cstdint>

#define N_NODES 100000
#define C_DIM   256
#define CSR_CAP 3400000
#define SCAN_B  1024

// GEMM tiling
#define BM 128
#define BN 128
#define BK 32
#define AS_STRIDE 129   // [k][m] floats, odd stride -> conflict-free transposed stores
#define BS_STRIDE 132   // [k][n] floats, float4-aligned rows

// ---------------- device scratch (no allocations allowed) ----------------
__device__ int    g_deg[N_NODES];
__device__ int    g_offs[N_NODES + 1];
__device__ int    g_cursor[N_NODES];
__device__ float  g_dis[N_NODES];
__device__ int    g_blockSums[SCAN_B];
__device__ int    g_csr_src[CSR_CAP];
__device__ float  g_csr_w[CSR_CAP];
__device__ __half g_bufT[(size_t)N_NODES * C_DIM];  // transformed features (fp16!)
__device__ float  g_bufH[(size_t)N_NODES * C_DIM];  // aggregated+activated features

// ---------------- degree / normalization ----------------
__global__ void k_deg_init() {
    int i = blockIdx.x * blockDim.x + threadIdx.x;
    if (i < N_NODES) g_deg[i] = 1;   // self-loop
}

__global__ void k_hist(const int* __restrict__ ei, int E) {
    for (int e = blockIdx.x * blockDim.x + threadIdx.x; e < E;
         e += gridDim.x * blockDim.x) {
        atomicAdd(&g_deg[ei[E + e]], 1);   // dst row
    }
}

// ---------------- exclusive scan of degrees -> CSR row offsets ----------------
__global__ void k_scan1() {
    __shared__ int s[SCAN_B];
    int tid = threadIdx.x;
    int i = blockIdx.x * SCAN_B + tid;
    int v = (i < N_NODES) ? g_deg[i] : 0;
    s[tid] = v;
    __syncthreads();
#pragma unroll
    for (int off = 1; off < SCAN_B; off <<= 1) {
        int a = (tid >= off) ? s[tid - off] : 0;
        __syncthreads();
        s[tid] += a;
        __syncthreads();
    }
    if (i < N_NODES) g_offs[i] = s[tid] - v;          // block-local exclusive
    if (tid == SCAN_B - 1) g_blockSums[blockIdx.x] = s[tid];
}

__global__ void k_scan2(int nblk) {
    __shared__ int s[SCAN_B];
    int tid = threadIdx.x;
    int v = (tid < nblk) ? g_blockSums[tid] : 0;
    s[tid] = v;
    __syncthreads();
#pragma unroll
    for (int off = 1; off < SCAN_B; off <<= 1) {
        int a = (tid >= off) ? s[tid - off] : 0;
        __syncthreads();
        s[tid] += a;
        __syncthreads();
    }
    if (tid < nblk) g_blockSums[tid] = s[tid] - v;     // exclusive block offsets
}

// scan finalize + deg_inv_sqrt + deterministic self-loop in each row's LAST slot
__global__ void k_scan3() {
    int i = blockIdx.x * blockDim.x + threadIdx.x;
    if (i < N_NODES) {
        int deg = g_deg[i];
        int e = g_offs[i] + g_blockSums[i >> 10];
        g_offs[i] = e;
        g_cursor[i] = e;
        float dis = rsqrtf((float)deg);
        g_dis[i] = dis;
        g_csr_src[e + deg - 1] = i;
        g_csr_w[e + deg - 1] = dis * dis;
        if (i == N_NODES - 1) g_offs[N_NODES] = e + deg;
    }
}

// ---------------- CSR fill ----------------
__global__ void k_fill(const int* __restrict__ ei, int E) {
    for (int e = blockIdx.x * blockDim.x + threadIdx.x; e < E;
         e += gridDim.x * blockDim.x) {
        int s = ei[e];
        int d = ei[E + e];
        int pos = atomicAdd(&g_cursor[d], 1);
        g_csr_src[pos] = s;
        g_csr_w[pos] = g_dis[s] * g_dis[d];
    }
}

// ---------------- tf32 tensor-core GEMM: g_bufT[M,256](fp16) = A[M,256] * B[256,256]
__device__ __forceinline__ uint32_t f2tf32(float f) {
    uint32_t u;
    asm("cvt.rna.tf32.f32 %0, %1;" : "=r"(u) : "f"(f));
    return u;
}

__device__ __forceinline__ void mma_tf32(float c[4], const uint32_t a[4],
                                         const uint32_t b[2]) {
    asm volatile(
        "mma.sync.aligned.m16n8k8.row.col.f32.tf32.tf32.f32 "
        "{%0,%1,%2,%3}, {%4,%5,%6,%7}, {%8,%9}, {%0,%1,%2,%3};"
        : "+f"(c[0]), "+f"(c[1]), "+f"(c[2]), "+f"(c[3])
        : "r"(a[0]), "r"(a[1]), "r"(a[2]), "r"(a[3]), "r"(b[0]), "r"(b[1]));
}

// 256 threads; 8 warps as 4(M) x 2(N); warp tile 32x64; mma m16n8k8.
__global__ __launch_bounds__(256, 2) void k_gemm_tf32(const float* __restrict__ A,
                                                      const float* __restrict__ Bw,
                                                      int M) {
    const float* Ap = A ? A : g_bufH;   // layer 2 reads g_bufH
    __shared__ uint32_t As[BK * AS_STRIDE];   // [k][m] tf32 bits
    __shared__ uint32_t Bs[BK * BS_STRIDE];   // [k][n] tf32 bits

    int tid = threadIdx.x;
    int lane = tid & 31;
    int warp = tid >> 5;
    int warpM = warp & 3;          // 0..3 -> 32 rows each
    int warpN = warp >> 2;         // 0..1 -> 64 cols each
    int rowBase = blockIdx.x * BM;
    int colBase = blockIdx.y * BN;

    int r = lane >> 2;             // 0..7
    int cq = lane & 3;             // 0..3

    float c[2][8][4];
#pragma unroll
    for (int mt = 0; mt < 2; mt++)
#pragma unroll
        for (int nt = 0; nt < 8; nt++)
#pragma unroll
            for (int j = 0; j < 4; j++) c[mt][nt][j] = 0.f;

    for (int k0 = 0; k0 < 256; k0 += BK) {
        // A tile: 128 rows x 32 k
#pragma unroll
        for (int it = 0; it < 4; it++) {
            int id = tid + it * 256;
            int k4 = id & 7;
            int m = id >> 3;
            int grow = rowBase + m;
            float4 v = make_float4(0.f, 0.f, 0.f, 0.f);
            if (grow < M)
                v = *(const float4*)(Ap + (size_t)grow * 256 + k0 + k4 * 4);
            As[(k4 * 4 + 0) * AS_STRIDE + m] = f2tf32(v.x);
            As[(k4 * 4 + 1) * AS_STRIDE + m] = f2tf32(v.y);
            As[(k4 * 4 + 2) * AS_STRIDE + m] = f2tf32(v.z);
            As[(k4 * 4 + 3) * AS_STRIDE + m] = f2tf32(v.w);
        }
        // B tile: 32 k x 128 n
#pragma unroll
        for (int it = 0; it < 4; it++) {
            int id = tid + it * 256;
            int n4 = id & 31;
            int k = id >> 5;
            float4 v = *(const float4*)(Bw + (size_t)(k0 + k) * 256 + colBase + n4 * 4);
            uint4 t;
            t.x = f2tf32(v.x); t.y = f2tf32(v.y); t.z = f2tf32(v.z); t.w = f2tf32(v.w);
            *(uint4*)&Bs[k * BS_STRIDE + n4 * 4] = t;
        }
        __syncthreads();

#pragma unroll
        for (int kk = 0; kk < BK; kk += 8) {
            uint32_t a[2][4], b[8][2];
#pragma unroll
            for (int mt = 0; mt < 2; mt++) {
                int m = warpM * 32 + mt * 16 + r;
                a[mt][0] = As[(kk + cq) * AS_STRIDE + m];
                a[mt][1] = As[(kk + cq) * AS_STRIDE + m + 8];
                a[mt][2] = As[(kk + cq + 4) * AS_STRIDE + m];
                a[mt][3] = As[(kk + cq + 4) * AS_STRIDE + m + 8];
            }
#pragma unroll
            for (int nt = 0; nt < 8; nt++) {
                int n = warpN * 64 + nt * 8 + r;
                b[nt][0] = Bs[(kk + cq) * BS_STRIDE + n];
                b[nt][1] = Bs[(kk + cq + 4) * BS_STRIDE + n];
            }
#pragma unroll
            for (int mt = 0; mt < 2; mt++)
#pragma unroll
                for (int nt = 0; nt < 8; nt++) mma_tf32(c[mt][nt], a[mt], b[nt]);
        }
        __syncthreads();
    }

    // epilogue: store fp16 pairs
#pragma unroll
    for (int mt = 0; mt < 2; mt++) {
        int grow = rowBase + warpM * 32 + mt * 16 + r;
#pragma unroll
        for (int nt = 0; nt < 8; nt++) {
            int gcol = colBase + warpN * 64 + nt * 8 + cq * 2;
            if (grow < M)
                *(__half2*)(g_bufT + (size_t)grow * 256 + gcol) =
                    __floats2half2_rn(c[mt][nt][0], c[mt][nt][1]);
            if (grow + 8 < M)
                *(__half2*)(g_bufT + (size_t)(grow + 8) * 256 + gcol) =
                    __floats2half2_rn(c[mt][nt][2], c[mt][nt][3]);
        }
    }
}

// ---------------- fp16 gather helper: accumulate one row into acc[8] ----------
__device__ __forceinline__ void acc_row(float acc[8], int s, float wt, int lane) {
    uint4 v = ((const uint4*)(g_bufT + (size_t)s * 256))[lane];
    const __half2* hp = (const __half2*)&v;
#pragma unroll
    for (int j = 0; j < 4; j++) {
        float2 f = __half22float2(hp[j]);
        acc[2 * j + 0] += wt * f.x;
        acc[2 * j + 1] += wt * f.y;
    }
}

// ---------------- aggregation (warp per node): g_bufH = relu(agg(g_bufT) + bias) ----
// lane covers features [lane*8, lane*8+8)
__global__ __launch_bounds__(256) void k_agg_relu(const float* __restrict__ bias) {
    int w = (blockIdx.x * blockDim.x + threadIdx.x) >> 5;
    int lane = threadIdx.x & 31;
    if (w >= N_NODES) return;
    int beg = g_offs[w], end = g_offs[w + 1];
    float acc[8];
#pragma unroll
    for (int j = 0; j < 8; j++) acc[j] = 0.f;
    int e = beg;
    for (; e + 2 <= end; e += 2) {
        int s0 = g_csr_src[e], s1 = g_csr_src[e + 1];
        float w0 = g_csr_w[e], w1 = g_csr_w[e + 1];
        acc_row(acc, s0, w0, lane);
        acc_row(acc, s1, w1, lane);
    }
    if (e < end) acc_row(acc, g_csr_src[e], g_csr_w[e], lane);

    float4 b0 = ((const float4*)bias)[lane * 2];
    float4 b1 = ((const float4*)bias)[lane * 2 + 1];
    float4 o0 = make_float4(fmaxf(acc[0] + b0.x, 0.f), fmaxf(acc[1] + b0.y, 0.f),
                            fmaxf(acc[2] + b0.z, 0.f), fmaxf(acc[3] + b0.w, 0.f));
    float4 o1 = make_float4(fmaxf(acc[4] + b1.x, 0.f), fmaxf(acc[5] + b1.y, 0.f),
                            fmaxf(acc[6] + b1.z, 0.f), fmaxf(acc[7] + b1.w, 0.f));
    float4* out = (float4*)(g_bufH + (size_t)w * 256);
    out[lane * 2] = o0;
    out[lane * 2 + 1] = o1;
}

// ---------------- agg layer 2 fused with final linear: out[i] = relu(agg+b2) @ Wl + bl
__global__ __launch_bounds__(256) void k_agg_final(const float* __restrict__ b2,
                                                   const float* __restrict__ Wl,
                                                   const float* __restrict__ bl,
                                                   float* __restrict__ out) {
    int w = (blockIdx.x * blockDim.x + threadIdx.x) >> 5;
    int lane = threadIdx.x & 31;
    if (w >= N_NODES) return;
    int beg = g_offs[w], end = g_offs[w + 1];
    float acc[8];
#pragma unroll
    for (int j = 0; j < 8; j++) acc[j] = 0.f;
    int e = beg;
    for (; e + 2 <= end; e += 2) {
        int s0 = g_csr_src[e], s1 = g_csr_src[e + 1];
        float w0 = g_csr_w[e], w1 = g_csr_w[e + 1];
        acc_row(acc, s0, w0, lane);
        acc_row(acc, s1, w1, lane);
    }
    if (e < end) acc_row(acc, g_csr_src[e], g_csr_w[e], lane);

    float4 b0 = ((const float4*)b2)[lane * 2];
    float4 b1 = ((const float4*)b2)[lane * 2 + 1];
    float4 w0 = ((const float4*)Wl)[lane * 2];
    float4 w1 = ((const float4*)Wl)[lane * 2 + 1];
    float s =
        fmaxf(acc[0] + b0.x, 0.f) * w0.x + fmaxf(acc[1] + b0.y, 0.f) * w0.y +
        fmaxf(acc[2] + b0.z, 0.f) * w0.z + fmaxf(acc[3] + b0.w, 0.f) * w0.w +
        fmaxf(acc[4] + b1.x, 0.f) * w1.x + fmaxf(acc[5] + b1.y, 0.f) * w1.y +
        fmaxf(acc[6] + b1.z, 0.f) * w1.z + fmaxf(acc[7] + b1.w, 0.f) * w1.w;
#pragma unroll
    for (int o = 16; o > 0; o >>= 1) s += __shfl_xor_sync(0xFFFFFFFFu, s, o);
    if (lane == 0) out[w] = s + bl[0];
}

// ---------------- launch ----------------
extern "C" void kernel_launch(void* const* d_in, const int* in_sizes, int n_in,
                              void* d_out, int out_size) {
    const float* x  = (const float*)d_in[0];
    const int*   ei = (const int*)d_in[1];     // edge_index is int32 (JAX x64 disabled)
    const float* W1 = (const float*)d_in[2];
    const float* b1 = (const float*)d_in[3];
    const float* W2 = (const float*)d_in[4];
    const float* b2 = (const float*)d_in[5];
    const float* Wl = (const float*)d_in[6];
    const float* bl = (const float*)d_in[7];
    float* out = (float*)d_out;

    int E = in_sizes[1] / 2;
    int nblk = (N_NODES + SCAN_B - 1) / SCAN_B;           // 98
    int node_blocks = (N_NODES + 255) / 256;              // 391
    int agg_blocks = (N_NODES * 32 + 255) / 256;          // 12500 (warp per node)

    // CSR build (shared by both conv layers)
    k_deg_init<<<node_blocks, 256>>>();
    k_hist<<<4096, 256>>>(ei, E);
    k_scan1<<<nblk, SCAN_B>>>();
    k_scan2<<<1, SCAN_B>>>(nblk);
    k_scan3<<<node_blocks, 256>>>();     // offsets + dis + self-loops
    k_fill<<<4096, 256>>>(ei, E);

    dim3 ggrid((N_NODES + BM - 1) / BM, 256 / BN);        // (782, 2)

    // layer 1: T = x @ W1 ; H = relu(agg(T) + b1)
    k_gemm_tf32<<<ggrid, 256>>>(x, W1, N_NODES);
    k_agg_relu<<<agg_blocks, 256>>>(b1);

    // layer 2: T = H @ W2 ; out = relu(agg(T) + b2) @ Wl + bl   (fused)
    k_gemm_tf32<<<ggrid, 256>>>(nullptr, W2, N_NODES);
    k_agg_final<<<agg_blocks, 256>>>(b2, Wl, bl, out);
}

// round 7
// speedup vs baseline: 2.0150x; 1.0944x over previous
#include <cuda_runtime.h>
#include <cuda_fp16.h>
#include <cuda_bf16.h>
#include <cstdint>

#define N_NODES 100000
#define C_DIM   256
#define CSR_CAP 3400000
#define SCAN_B  1024

// GEMM tiling
#define BM 128
#define BN 128
#define BK 32
#define AS_STRIDE 129   // [k][m], odd stride -> conflict-free transposed stores
#define BS_STRIDE 132   // [k][n], float4-aligned rows

// ---------------- device scratch (no allocations allowed) ----------------
__device__ int    g_deg[N_NODES];
__device__ int    g_offs[N_NODES + 1];
__device__ int    g_cursor[N_NODES];
__device__ float  g_dis[N_NODES];
__device__ int    g_blockSums[SCAN_B];
__device__ int    g_csr_src[CSR_CAP];
__device__ __half g_bufT[(size_t)N_NODES * C_DIM];  // transformed features (fp16)
__device__ __half g_bufH[(size_t)N_NODES * C_DIM];  // layer-1 output (fp16)

// ---------------- degree / normalization ----------------
__global__ void k_deg_init() {
    int i = blockIdx.x * blockDim.x + threadIdx.x;
    if (i < N_NODES) g_deg[i] = 1;   // self-loop
}

__global__ void k_hist(const int* __restrict__ ei, int E) {
    for (int e = blockIdx.x * blockDim.x + threadIdx.x; e < E;
         e += gridDim.x * blockDim.x) {
        atomicAdd(&g_deg[ei[E + e]], 1);   // dst row
    }
}

// ---------------- exclusive scan of degrees -> CSR row offsets ----------------
__global__ void k_scan1() {
    __shared__ int s[SCAN_B];
    int tid = threadIdx.x;
    int i = blockIdx.x * SCAN_B + tid;
    int v = (i < N_NODES) ? g_deg[i] : 0;
    s[tid] = v;
    __syncthreads();
#pragma unroll
    for (int off = 1; off < SCAN_B; off <<= 1) {
        int a = (tid >= off) ? s[tid - off] : 0;
        __syncthreads();
        s[tid] += a;
        __syncthreads();
    }
    if (i < N_NODES) g_offs[i] = s[tid] - v;          // block-local exclusive
    if (tid == SCAN_B - 1) g_blockSums[blockIdx.x] = s[tid];
}

__global__ void k_scan2(int nblk) {
    __shared__ int s[SCAN_B];
    int tid = threadIdx.x;
    int v = (tid < nblk) ? g_blockSums[tid] : 0;
    s[tid] = v;
    __syncthreads();
#pragma unroll
    for (int off = 1; off < SCAN_B; off <<= 1) {
        int a = (tid >= off) ? s[tid - off] : 0;
        __syncthreads();
        s[tid] += a;
        __syncthreads();
    }
    if (tid < nblk) g_blockSums[tid] = s[tid] - v;     // exclusive block offsets
}

// scan finalize + deg_inv_sqrt + deterministic self-loop in each row's LAST slot
// (k_fill atomically fills slots offs[i]..offs[i]+deg-2; last slot = self-loop)
__global__ void k_scan3() {
    int i = blockIdx.x * blockDim.x + threadIdx.x;
    if (i < N_NODES) {
        int deg = g_deg[i];
        int e = g_offs[i] + g_blockSums[i >> 10];
        g_offs[i] = e;
        g_cursor[i] = e;
        g_dis[i] = rsqrtf((float)deg);
        g_csr_src[e + deg - 1] = i;            // self-loop; weight = dis[i]^2 falls out
        if (i == N_NODES - 1) g_offs[N_NODES] = e + deg;
    }
}

// ---------------- CSR fill (src only; weights recomputed in agg) ----------------
__global__ void k_fill(const int* __restrict__ ei, int E) {
    for (int e = blockIdx.x * blockDim.x + threadIdx.x; e < E;
         e += gridDim.x * blockDim.x) {
        int s = ei[e];
        int d = ei[E + e];
        int pos = atomicAdd(&g_cursor[d], 1);
        g_csr_src[pos] = s;
    }
}

// ---------------- tf32 tensor-core GEMM: g_bufT[M,256](fp16) = A[M,256] * B ------
__device__ __forceinline__ uint32_t f2tf32(float f) {
    uint32_t u;
    asm("cvt.rna.tf32.f32 %0, %1;" : "=r"(u) : "f"(f));
    return u;
}

__device__ __forceinline__ void mma_tf32(float c[4], const uint32_t a[4],
                                         const uint32_t b[2]) {
    asm volatile(
        "mma.sync.aligned.m16n8k8.row.col.f32.tf32.tf32.f32 "
        "{%0,%1,%2,%3}, {%4,%5,%6,%7}, {%8,%9}, {%0,%1,%2,%3};"
        : "+f"(c[0]), "+f"(c[1]), "+f"(c[2]), "+f"(c[3])
        : "r"(a[0]), "r"(a[1]), "r"(a[2]), "r"(a[3]), "r"(b[0]), "r"(b[1]));
}

__device__ __forceinline__ float4 ldA4(const float* p) {
    return *(const float4*)p;
}
__device__ __forceinline__ float4 ldA4(const __half* p) {
    uint2 u = *(const uint2*)p;
    float2 f0 = __half22float2(*(__half2*)&u.x);
    float2 f1 = __half22float2(*(__half2*)&u.y);
    return make_float4(f0.x, f0.y, f1.x, f1.y);
}

// 256 threads; 8 warps as 4(M) x 2(N); warp tile 32x64; mma m16n8k8.
template <typename TA>
__global__ __launch_bounds__(256, 2) void k_gemm_tf32(const TA* __restrict__ A,
                                                      const float* __restrict__ Bw,
                                                      int M) {
    const TA* Ap = A ? A : (const TA*)g_bufH;   // layer 2 reads g_bufH (fp16)
    __shared__ uint32_t As[BK * AS_STRIDE];     // [k][m] tf32 bits
    __shared__ uint32_t Bs[BK * BS_STRIDE];     // [k][n] tf32 bits

    int tid = threadIdx.x;
    int lane = tid & 31;
    int warp = tid >> 5;
    int warpM = warp & 3;
    int warpN = warp >> 2;
    int rowBase = blockIdx.x * BM;
    int colBase = blockIdx.y * BN;

    int r = lane >> 2;             // 0..7
    int cq = lane & 3;             // 0..3

    float c[2][8][4];
#pragma unroll
    for (int mt = 0; mt < 2; mt++)
#pragma unroll
        for (int nt = 0; nt < 8; nt++)
#pragma unroll
            for (int j = 0; j < 4; j++) c[mt][nt][j] = 0.f;

    for (int k0 = 0; k0 < 256; k0 += BK) {
        // A tile: 128 rows x 32 k
#pragma unroll
        for (int it = 0; it < 4; it++) {
            int id = tid + it * 256;
            int k4 = id & 7;
            int m = id >> 3;
            int grow = rowBase + m;
            float4 v = make_float4(0.f, 0.f, 0.f, 0.f);
            if (grow < M)
                v = ldA4(Ap + (size_t)grow * 256 + k0 + k4 * 4);
            As[(k4 * 4 + 0) * AS_STRIDE + m] = f2tf32(v.x);
            As[(k4 * 4 + 1) * AS_STRIDE + m] = f2tf32(v.y);
            As[(k4 * 4 + 2) * AS_STRIDE + m] = f2tf32(v.z);
            As[(k4 * 4 + 3) * AS_STRIDE + m] = f2tf32(v.w);
        }
        // B tile: 32 k x 128 n
#pragma unroll
        for (int it = 0; it < 4; it++) {
            int id = tid + it * 256;
            int n4 = id & 31;
            int k = id >> 5;
            float4 v = *(const float4*)(Bw + (size_t)(k0 + k) * 256 + colBase + n4 * 4);
            uint4 t;
            t.x = f2tf32(v.x); t.y = f2tf32(v.y); t.z = f2tf32(v.z); t.w = f2tf32(v.w);
            *(uint4*)&Bs[k * BS_STRIDE + n4 * 4] = t;
        }
        __syncthreads();

#pragma unroll
        for (int kk = 0; kk < BK; kk += 8) {
            uint32_t a[2][4], b[8][2];
#pragma unroll
            for (int mt = 0; mt < 2; mt++) {
                int m = warpM * 32 + mt * 16 + r;
                a[mt][0] = As[(kk + cq) * AS_STRIDE + m];
                a[mt][1] = As[(kk + cq) * AS_STRIDE + m + 8];
                a[mt][2] = As[(kk + cq + 4) * AS_STRIDE + m];
                a[mt][3] = As[(kk + cq + 4) * AS_STRIDE + m + 8];
            }
#pragma unroll
            for (int nt = 0; nt < 8; nt++) {
                int n = warpN * 64 + nt * 8 + r;
                b[nt][0] = Bs[(kk + cq) * BS_STRIDE + n];
                b[nt][1] = Bs[(kk + cq + 4) * BS_STRIDE + n];
            }
#pragma unroll
            for (int mt = 0; mt < 2; mt++)
#pragma unroll
                for (int nt = 0; nt < 8; nt++) mma_tf32(c[mt][nt], a[mt], b[nt]);
        }
        __syncthreads();
    }

    // epilogue: store fp16 pairs
#pragma unroll
    for (int mt = 0; mt < 2; mt++) {
        int grow = rowBase + warpM * 32 + mt * 16 + r;
#pragma unroll
        for (int nt = 0; nt < 8; nt++) {
            int gcol = colBase + warpN * 64 + nt * 8 + cq * 2;
            if (grow < M)
                *(__half2*)(g_bufT + (size_t)grow * 256 + gcol) =
                    __floats2half2_rn(c[mt][nt][0], c[mt][nt][1]);
            if (grow + 8 < M)
                *(__half2*)(g_bufT + (size_t)(grow + 8) * 256 + gcol) =
                    __floats2half2_rn(c[mt][nt][2], c[mt][nt][3]);
        }
    }
}

// ---------------- fp16 gather helper: accumulate one row into acc[8] ----------
__device__ __forceinline__ void acc_row(float acc[8], int s, float wt, int lane) {
    uint4 v = ((const uint4*)(g_bufT + (size_t)s * 256))[lane];
    const __half2* hp = (const __half2*)&v;
#pragma unroll
    for (int j = 0; j < 4; j++) {
        float2 f = __half22float2(hp[j]);
        acc[2 * j + 0] += wt * f.x;
        acc[2 * j + 1] += wt * f.y;
    }
}

// edge loop shared by both agg kernels: unroll-4, indices+weights prefetched
__device__ __forceinline__ void agg_edges(float acc[8], int beg, int end,
                                          float disw, int lane) {
    int e = beg;
    for (; e + 4 <= end; e += 4) {
        int s0 = g_csr_src[e + 0], s1 = g_csr_src[e + 1];
        int s2 = g_csr_src[e + 2], s3 = g_csr_src[e + 3];
        float w0 = g_dis[s0] * disw, w1 = g_dis[s1] * disw;
        float w2 = g_dis[s2] * disw, w3 = g_dis[s3] * disw;
        acc_row(acc, s0, w0, lane);
        acc_row(acc, s1, w1, lane);
        acc_row(acc, s2, w2, lane);
        acc_row(acc, s3, w3, lane);
    }
    for (; e < end; e++) {
        int s = g_csr_src[e];
        acc_row(acc, s, g_dis[s] * disw, lane);
    }
}

// ---------------- aggregation (warp per node): g_bufH = relu(agg(g_bufT) + bias) ----
// lane covers features [lane*8, lane*8+8)
__global__ __launch_bounds__(256) void k_agg_relu(const float* __restrict__ bias) {
    int w = (blockIdx.x * blockDim.x + threadIdx.x) >> 5;
    int lane = threadIdx.x & 31;
    if (w >= N_NODES) return;
    int beg = g_offs[w], end = g_offs[w + 1];
    float disw = g_dis[w];
    float acc[8];
#pragma unroll
    for (int j = 0; j < 8; j++) acc[j] = 0.f;
    agg_edges(acc, beg, end, disw, lane);

    float4 b0 = ((const float4*)bias)[lane * 2];
    float4 b1 = ((const float4*)bias)[lane * 2 + 1];
    __half2 h[4];
    h[0] = __floats2half2_rn(fmaxf(acc[0] + b0.x, 0.f), fmaxf(acc[1] + b0.y, 0.f));
    h[1] = __floats2half2_rn(fmaxf(acc[2] + b0.z, 0.f), fmaxf(acc[3] + b0.w, 0.f));
    h[2] = __floats2half2_rn(fmaxf(acc[4] + b1.x, 0.f), fmaxf(acc[5] + b1.y, 0.f));
    h[3] = __floats2half2_rn(fmaxf(acc[6] + b1.z, 0.f), fmaxf(acc[7] + b1.w, 0.f));
    ((uint4*)(g_bufH + (size_t)w * 256))[lane] = *(uint4*)h;
}

// ---------------- agg layer 2 fused with final linear: out[i] = relu(agg+b2) @ Wl + bl
__global__ __launch_bounds__(256) void k_agg_final(const float* __restrict__ b2,
                                                   const float* __restrict__ Wl,
                                                   const float* __restrict__ bl,
                                                   float* __restrict__ out) {
    int w = (blockIdx.x * blockDim.x + threadIdx.x) >> 5;
    int lane = threadIdx.x & 31;
    if (w >= N_NODES) return;
    int beg = g_offs[w], end = g_offs[w + 1];
    float disw = g_dis[w];
    float acc[8];
#pragma unroll
    for (int j = 0; j < 8; j++) acc[j] = 0.f;
    agg_edges(acc, beg, end, disw, lane);

    float4 b0 = ((const float4*)b2)[lane * 2];
    float4 b1 = ((const float4*)b2)[lane * 2 + 1];
    float4 w0 = ((const float4*)Wl)[lane * 2];
    float4 w1 = ((const float4*)Wl)[lane * 2 + 1];
    float s =
        fmaxf(acc[0] + b0.x, 0.f) * w0.x + fmaxf(acc[1] + b0.y, 0.f) * w0.y +
        fmaxf(acc[2] + b0.z, 0.f) * w0.z + fmaxf(acc[3] + b0.w, 0.f) * w0.w +
        fmaxf(acc[4] + b1.x, 0.f) * w1.x + fmaxf(acc[5] + b1.y, 0.f) * w1.y +
        fmaxf(acc[6] + b1.z, 0.f) * w1.z + fmaxf(acc[7] + b1.w, 0.f) * w1.w;
#pragma unroll
    for (int o = 16; o > 0; o >>= 1) s += __shfl_xor_sync(0xFFFFFFFFu, s, o);
    if (lane == 0) out[w] = s + bl[0];
}

// ---------------- launch ----------------
extern "C" void kernel_launch(void* const* d_in, const int* in_sizes, int n_in,
                              void* d_out, int out_size) {
    const float* x  = (const float*)d_in[0];
    const int*   ei = (const int*)d_in[1];     // edge_index is int32 (JAX x64 disabled)
    const float* W1 = (const float*)d_in[2];
    const float* b1 = (const float*)d_in[3];
    const float* W2 = (const float*)d_in[4];
    const float* b2 = (const float*)d_in[5];
    const float* Wl = (const float*)d_in[6];
    const float* bl = (const float*)d_in[7];
    float* out = (float*)d_out;

    int E = in_sizes[1] / 2;
    int nblk = (N_NODES + SCAN_B - 1) / SCAN_B;           // 98
    int node_blocks = (N_NODES + 255) / 256;              // 391
    int agg_blocks = (N_NODES * 32 + 255) / 256;          // 12500 (warp per node)

    // CSR build (shared by both conv layers)
    k_deg_init<<<node_blocks, 256>>>();
    k_hist<<<4096, 256>>>(ei, E);
    k_scan1<<<nblk, SCAN_B>>>();
    k_scan2<<<1, SCAN_B>>>(nblk);
    k_scan3<<<node_blocks, 256>>>();     // offsets + dis + self-loops
    k_fill<<<4096, 256>>>(ei, E);

    dim3 ggrid((N_NODES + BM - 1) / BM, 256 / BN);        // (782, 2)

    // layer 1: T = x @ W1 ; H = relu(agg(T) + b1)
    k_gemm_tf32<float><<<ggrid, 256>>>(x, W1, N_NODES);
    k_agg_relu<<<agg_blocks, 256>>>(b1);

    // layer 2: T = H @ W2 ; out = relu(agg(T) + b2) @ Wl + bl   (fused)
    k_gemm_tf32<__half><<<ggrid, 256>>>((const __half*)nullptr, W2, N_NODES);
    k_agg_final<<<agg_blocks, 256>>>(b2, Wl, bl, out);
}

// round 8
// speedup vs baseline: 2.0210x; 1.0029x over previous
#include <cuda_runtime.h>
#include <cuda_fp16.h>
#include <cuda_bf16.h>
#include <cstdint>

#define N_NODES 100000
#define C_DIM   256
#define CSR_CAP 3400000
#define SCAN_B  1024

// GEMM tiling
#define BM 128
#define BN 128
#define BK 32
#define AS_STRIDE 129   // [k][m], odd stride -> conflict-free transposed stores
#define BS_STRIDE 132   // [k][n], float4-aligned rows

#define AUX_BLOCKS 512
#define HALF_TILES 391   // row tiles per GEMM1 half (391*128 = 50048)
#define FULL_TILES 782

// ---------------- device scratch (no allocations allowed) ----------------
__device__ int    g_deg[N_NODES];
__device__ int    g_offs[N_NODES + 1];
__device__ int    g_cursor[N_NODES];
__device__ float  g_dis[N_NODES];
__device__ int    g_blockSums[SCAN_B];
__device__ int    g_csr_src[CSR_CAP];
__device__ __half g_bufT[(size_t)N_NODES * C_DIM];  // transformed features (fp16)
__device__ __half g_bufH[(size_t)N_NODES * C_DIM];  // layer-1 output (fp16)

// ---------------- degree init ----------------
__global__ void k_deg_init() {
    int i = blockIdx.x * blockDim.x + threadIdx.x;
    if (i < N_NODES) g_deg[i] = 1;   // self-loop
}

// ---------------- exclusive scan of degrees -> CSR row offsets ----------------
__global__ void k_scan1() {
    __shared__ int s[SCAN_B];
    int tid = threadIdx.x;
    int i = blockIdx.x * SCAN_B + tid;
    int v = (i < N_NODES) ? g_deg[i] : 0;
    s[tid] = v;
    __syncthreads();
#pragma unroll
    for (int off = 1; off < SCAN_B; off <<= 1) {
        int a = (tid >= off) ? s[tid - off] : 0;
        __syncthreads();
        s[tid] += a;
        __syncthreads();
    }
    if (i < N_NODES) g_offs[i] = s[tid] - v;          // block-local exclusive
    if (tid == SCAN_B - 1) g_blockSums[blockIdx.x] = s[tid];
}

__global__ void k_scan2(int nblk) {
    __shared__ int s[SCAN_B];
    int tid = threadIdx.x;
    int v = (tid < nblk) ? g_blockSums[tid] : 0;
    s[tid] = v;
    __syncthreads();
#pragma unroll
    for (int off = 1; off < SCAN_B; off <<= 1) {
        int a = (tid >= off) ? s[tid - off] : 0;
        __syncthreads();
        s[tid] += a;
        __syncthreads();
    }
    if (tid < nblk) g_blockSums[tid] = s[tid] - v;     // exclusive block offsets
}

// scan finalize + deg_inv_sqrt + deterministic self-loop in each row's LAST slot
// (fill atomically takes slots offs[i]..offs[i]+deg-2; last slot = self-loop)
__global__ void k_scan3() {
    int i = blockIdx.x * blockDim.x + threadIdx.x;
    if (i < N_NODES) {
        int deg = g_deg[i];
        int e = g_offs[i] + g_blockSums[i >> 10];
        g_offs[i] = e;
        g_cursor[i] = e;
        g_dis[i] = rsqrtf((float)deg);
        g_csr_src[e + deg - 1] = i;            // self-loop; weight dis[i]^2 falls out
        if (i == N_NODES - 1) g_offs[N_NODES] = e + deg;
    }
}

// ---------------- tf32 tensor-core GEMM (+ optional fused aux CTAs) ----------
__device__ __forceinline__ uint32_t f2tf32(float f) {
    uint32_t u;
    asm("cvt.rna.tf32.f32 %0, %1;" : "=r"(u) : "f"(f));
    return u;
}

__device__ __forceinline__ void mma_tf32(float c[4], const uint32_t a[4],
                                         const uint32_t b[2]) {
    asm volatile(
        "mma.sync.aligned.m16n8k8.row.col.f32.tf32.tf32.f32 "
        "{%0,%1,%2,%3}, {%4,%5,%6,%7}, {%8,%9}, {%0,%1,%2,%3};"
        : "+f"(c[0]), "+f"(c[1]), "+f"(c[2]), "+f"(c[3])
        : "r"(a[0]), "r"(a[1]), "r"(a[2]), "r"(a[3]), "r"(b[0]), "r"(b[1]));
}

__device__ __forceinline__ float4 ldA4(const float* p) {
    return *(const float4*)p;
}
__device__ __forceinline__ float4 ldA4(const __half* p) {
    uint2 u = *(const uint2*)p;
    float2 f0 = __half22float2(*(__half2*)&u.x);
    float2 f1 = __half22float2(*(__half2*)&u.y);
    return make_float4(f0.x, f0.y, f1.x, f1.y);
}

// AUX: 0 = none, 1 = degree histogram, 2 = CSR fill.
// Aux CTAs occupy block indices [0, auxBlocks) so they launch in the first waves
// and overlap with the GEMM tiles that follow.
template <typename TA, int AUX>
__global__ __launch_bounds__(256, 2) void k_gemm_aux(const TA* __restrict__ A,
                                                     const float* __restrict__ Bw,
                                                     int M, int rowTileOff,
                                                     int nRowTiles,
                                                     const int* __restrict__ ei,
                                                     int E, int auxBlocks) {
    if (AUX != 0 && (int)blockIdx.x < auxBlocks) {
        int t = blockIdx.x * 256 + threadIdx.x;
        int stride = auxBlocks * 256;
        if (AUX == 1) {
            for (int e = t; e < E; e += stride)
                atomicAdd(&g_deg[ei[E + e]], 1);          // dst histogram
        } else {
            for (int e = t; e < E; e += stride) {
                int s = ei[e];
                int d = ei[E + e];
                int pos = atomicAdd(&g_cursor[d], 1);
                g_csr_src[pos] = s;
            }
        }
        return;
    }

    const TA* Ap = A ? A : (const TA*)g_bufH;   // layer 2 reads g_bufH (fp16)
    __shared__ uint32_t As[BK * AS_STRIDE];     // [k][m] tf32 bits
    __shared__ uint32_t Bs[BK * BS_STRIDE];     // [k][n] tf32 bits

    int tile = blockIdx.x - auxBlocks;
    int rowBase = (rowTileOff + tile % nRowTiles) * BM;
    int colBase = (tile / nRowTiles) * BN;

    int tid = threadIdx.x;
    int lane = tid & 31;
    int warp = tid >> 5;
    int warpM = warp & 3;
    int warpN = warp >> 2;

    int r = lane >> 2;             // 0..7
    int cq = lane & 3;             // 0..3

    float c[2][8][4];
#pragma unroll
    for (int mt = 0; mt < 2; mt++)
#pragma unroll
        for (int nt = 0; nt < 8; nt++)
#pragma unroll
            for (int j = 0; j < 4; j++) c[mt][nt][j] = 0.f;

    for (int k0 = 0; k0 < 256; k0 += BK) {
        // A tile: 128 rows x 32 k
#pragma unroll
        for (int it = 0; it < 4; it++) {
            int id = tid + it * 256;
            int k4 = id & 7;
            int m = id >> 3;
            int grow = rowBase + m;
            float4 v = make_float4(0.f, 0.f, 0.f, 0.f);
            if (grow < M)
                v = ldA4(Ap + (size_t)grow * 256 + k0 + k4 * 4);
            As[(k4 * 4 + 0) * AS_STRIDE + m] = f2tf32(v.x);
            As[(k4 * 4 + 1) * AS_STRIDE + m] = f2tf32(v.y);
            As[(k4 * 4 + 2) * AS_STRIDE + m] = f2tf32(v.z);
            As[(k4 * 4 + 3) * AS_STRIDE + m] = f2tf32(v.w);
        }
        // B tile: 32 k x 128 n
#pragma unroll
        for (int it = 0; it < 4; it++) {
            int id = tid + it * 256;
            int n4 = id & 31;
            int k = id >> 5;
            float4 v = *(const float4*)(Bw + (size_t)(k0 + k) * 256 + colBase + n4 * 4);
            uint4 t;
            t.x = f2tf32(v.x); t.y = f2tf32(v.y); t.z = f2tf32(v.z); t.w = f2tf32(v.w);
            *(uint4*)&Bs[k * BS_STRIDE + n4 * 4] = t;
        }
        __syncthreads();

#pragma unroll
        for (int kk = 0; kk < BK; kk += 8) {
            uint32_t a[2][4], b[8][2];
#pragma unroll
            for (int mt = 0; mt < 2; mt++) {
                int m = warpM * 32 + mt * 16 + r;
                a[mt][0] = As[(kk + cq) * AS_STRIDE + m];
                a[mt][1] = As[(kk + cq) * AS_STRIDE + m + 8];
                a[mt][2] = As[(kk + cq + 4) * AS_STRIDE + m];
                a[mt][3] = As[(kk + cq + 4) * AS_STRIDE + m + 8];
            }
#pragma unroll
            for (int nt = 0; nt < 8; nt++) {
                int n = warpN * 64 + nt * 8 + r;
                b[nt][0] = Bs[(kk + cq) * BS_STRIDE + n];
                b[nt][1] = Bs[(kk + cq + 4) * BS_STRIDE + n];
            }
#pragma unroll
            for (int mt = 0; mt < 2; mt++)
#pragma unroll
                for (int nt = 0; nt < 8; nt++) mma_tf32(c[mt][nt], a[mt], b[nt]);
        }
        __syncthreads();
    }

    // epilogue: store fp16 pairs
#pragma unroll
    for (int mt = 0; mt < 2; mt++) {
        int grow = rowBase + warpM * 32 + mt * 16 + r;
#pragma unroll
        for (int nt = 0; nt < 8; nt++) {
            int gcol = colBase + warpN * 64 + nt * 8 + cq * 2;
            if (grow < M)
                *(__half2*)(g_bufT + (size_t)grow * 256 + gcol) =
                    __floats2half2_rn(c[mt][nt][0], c[mt][nt][1]);
            if (grow + 8 < M)
                *(__half2*)(g_bufT + (size_t)(grow + 8) * 256 + gcol) =
                    __floats2half2_rn(c[mt][nt][2], c[mt][nt][3]);
        }
    }
}

// ---------------- fp16 gather helper: accumulate one row into acc[8] ----------
__device__ __forceinline__ void acc_row(float acc[8], int s, float wt, int lane) {
    uint4 v = ((const uint4*)(g_bufT + (size_t)s * 256))[lane];
    const __half2* hp = (const __half2*)&v;
#pragma unroll
    for (int j = 0; j < 4; j++) {
        float2 f = __half22float2(hp[j]);
        acc[2 * j + 0] += wt * f.x;
        acc[2 * j + 1] += wt * f.y;
    }
}

// edge loop shared by both agg kernels: unroll-4, indices+weights prefetched
__device__ __forceinline__ void agg_edges(float acc[8], int beg, int end,
                                          float disw, int lane) {
    int e = beg;
    for (; e + 4 <= end; e += 4) {
        int s0 = g_csr_src[e + 0], s1 = g_csr_src[e + 1];
        int s2 = g_csr_src[e + 2], s3 = g_csr_src[e + 3];
        float w0 = g_dis[s0] * disw, w1 = g_dis[s1] * disw;
        float w2 = g_dis[s2] * disw, w3 = g_dis[s3] * disw;
        acc_row(acc, s0, w0, lane);
        acc_row(acc, s1, w1, lane);
        acc_row(acc, s2, w2, lane);
        acc_row(acc, s3, w3, lane);
    }
    for (; e < end; e++) {
        int s = g_csr_src[e];
        acc_row(acc, s, g_dis[s] * disw, lane);
    }
}

// ---------------- aggregation (warp per node): g_bufH = relu(agg(g_bufT) + bias) ----
__global__ __launch_bounds__(256) void k_agg_relu(const float* __restrict__ bias) {
    int w = (blockIdx.x * blockDim.x + threadIdx.x) >> 5;
    int lane = threadIdx.x & 31;
    if (w >= N_NODES) return;
    int beg = g_offs[w], end = g_offs[w + 1];
    float disw = g_dis[w];
    float acc[8];
#pragma unroll
    for (int j = 0; j < 8; j++) acc[j] = 0.f;
    agg_edges(acc, beg, end, disw, lane);

    float4 b0 = ((const float4*)bias)[lane * 2];
    float4 b1 = ((const float4*)bias)[lane * 2 + 1];
    __half2 h[4];
    h[0] = __floats2half2_rn(fmaxf(acc[0] + b0.x, 0.f), fmaxf(acc[1] + b0.y, 0.f));
    h[1] = __floats2half2_rn(fmaxf(acc[2] + b0.z, 0.f), fmaxf(acc[3] + b0.w, 0.f));
    h[2] = __floats2half2_rn(fmaxf(acc[4] + b1.x, 0.f), fmaxf(acc[5] + b1.y, 0.f));
    h[3] = __floats2half2_rn(fmaxf(acc[6] + b1.z, 0.f), fmaxf(acc[7] + b1.w, 0.f));
    ((uint4*)(g_bufH + (size_t)w * 256))[lane] = *(uint4*)h;
}

// ---------------- agg layer 2 fused with final linear: out[i] = relu(agg+b2) @ Wl + bl
__global__ __launch_bounds__(256) void k_agg_final(const float* __restrict__ b2,
                                                   const float* __restrict__ Wl,
                                                   const float* __restrict__ bl,
                                                   float* __restrict__ out) {
    int w = (blockIdx.x * blockDim.x + threadIdx.x) >> 5;
    int lane = threadIdx.x & 31;
    if (w >= N_NODES) return;
    int beg = g_offs[w], end = g_offs[w + 1];
    float disw = g_dis[w];
    float acc[8];
#pragma unroll
    for (int j = 0; j < 8; j++) acc[j] = 0.f;
    agg_edges(acc, beg, end, disw, lane);

    float4 b0 = ((const float4*)b2)[lane * 2];
    float4 b1 = ((const float4*)b2)[lane * 2 + 1];
    float4 w0 = ((const float4*)Wl)[lane * 2];
    float4 w1 = ((const float4*)Wl)[lane * 2 + 1];
    float s =
        fmaxf(acc[0] + b0.x, 0.f) * w0.x + fmaxf(acc[1] + b0.y, 0.f) * w0.y +
        fmaxf(acc[2] + b0.z, 0.f) * w0.z + fmaxf(acc[3] + b0.w, 0.f) * w0.w +
        fmaxf(acc[4] + b1.x, 0.f) * w1.x + fmaxf(acc[5] + b1.y, 0.f) * w1.y +
        fmaxf(acc[6] + b1.z, 0.f) * w1.z + fmaxf(acc[7] + b1.w, 0.f) * w1.w;
#pragma unroll
    for (int o = 16; o > 0; o >>= 1) s += __shfl_xor_sync(0xFFFFFFFFu, s, o);
    if (lane == 0) out[w] = s + bl[0];
}

// ---------------- launch ----------------
extern "C" void kernel_launch(void* const* d_in, const int* in_sizes, int n_in,
                              void* d_out, int out_size) {
    const float* x  = (const float*)d_in[0];
    const int*   ei = (const int*)d_in[1];     // edge_index is int32 (JAX x64 disabled)
    const float* W1 = (const float*)d_in[2];
    const float* b1 = (const float*)d_in[3];
    const float* W2 = (const float*)d_in[4];
    const float* b2 = (const float*)d_in[5];
    const float* Wl = (const float*)d_in[6];
    const float* bl = (const float*)d_in[7];
    float* out = (float*)d_out;

    int E = in_sizes[1] / 2;
    int nblk = (N_NODES + SCAN_B - 1) / SCAN_B;           // 98
    int node_blocks = (N_NODES + 255) / 256;              // 391
    int agg_blocks = (N_NODES * 32 + 255) / 256;          // 12500 (warp per node)

    k_deg_init<<<node_blocks, 256>>>();

    // GEMM1 first half (rows [0, 50048)) overlapped with degree histogram
    k_gemm_aux<float, 1><<<AUX_BLOCKS + HALF_TILES * 2, 256>>>(
        x, W1, N_NODES, 0, HALF_TILES, ei, E, AUX_BLOCKS);

    // serial neck: offsets + dis + self-loops (~15 us)
    k_scan1<<<nblk, SCAN_B>>>();
    k_scan2<<<1, SCAN_B>>>(nblk);
    k_scan3<<<node_blocks, 256>>>();

    // GEMM1 second half (rows [50048, 100000)) overlapped with CSR fill
    k_gemm_aux<float, 2><<<AUX_BLOCKS + HALF_TILES * 2, 256>>>(
        x, W1, N_NODES, HALF_TILES, HALF_TILES, ei, E, AUX_BLOCKS);

    // layer 1 aggregation: H = relu(agg(T) + b1)
    k_agg_relu<<<agg_blocks, 256>>>(b1);

    // layer 2: T = H @ W2 ; out = relu(agg(T) + b2) @ Wl + bl   (fused)
    k_gemm_aux<__half, 0><<<FULL_TILES * 2, 256>>>(
        (const __half*)nullptr, W2, N_NODES, 0, FULL_TILES, nullptr, 0, 0);
    k_agg_final<<<agg_blocks, 256>>>(b2, Wl, bl, out);
}